// round 16
// baseline (speedup 1.0000x reference)
#include <cuda_runtime.h>
#include <math.h>

#define BATCH 512
#define SEQ   256
#define EMB   384
#define MTOT  (BATCH*SEQ)

__device__ float g_qkv[(size_t)MTOT * 3 * EMB];   // tf32-rounded qkv
__device__ float g_o  [(size_t)MTOT * EMB];       // tf32-rounded attention out

__device__ __forceinline__ unsigned f2tf32(float v) {
    unsigned r;
    asm("cvt.rna.tf32.f32 %0, %1;" : "=r"(r) : "f"(v));
    return r;
}

__device__ __forceinline__ void mma_tf32(float c[4], const unsigned a[4], const unsigned b[2]) {
    asm volatile(
        "mma.sync.aligned.m16n8k8.row.col.f32.tf32.tf32.f32 "
        "{%0,%1,%2,%3}, {%4,%5,%6,%7}, {%8,%9}, {%0,%1,%2,%3};"
        : "+f"(c[0]), "+f"(c[1]), "+f"(c[2]), "+f"(c[3])
        : "r"(a[0]), "r"(a[1]), "r"(a[2]), "r"(a[3]), "r"(b[0]), "r"(b[1]));
}

__device__ __forceinline__ void ldsmA(unsigned a[4], const unsigned* base, int stride,
                                      int mbase, int kk0, int lane) {
    const unsigned* p = base + (size_t)(mbase + (lane & 15)) * stride + kk0 + ((lane >> 4) << 2);
    unsigned addr = (unsigned)__cvta_generic_to_shared(p);
    asm volatile("ldmatrix.sync.aligned.m8n8.x4.shared.b16 {%0,%1,%2,%3}, [%4];"
                 : "=r"(a[0]), "=r"(a[1]), "=r"(a[2]), "=r"(a[3]) : "r"(addr));
}

__device__ __forceinline__ void cpa16(unsigned dst, const void* src) {
    asm volatile("cp.async.cg.shared.global [%0], [%1], 16;" :: "r"(dst), "l"(src));
}
#define CP_COMMIT() asm volatile("cp.async.commit_group;")
#define CP_WAIT0()  asm volatile("cp.async.wait_group 0;")

// ============================ dense GEMM (qkv, proj) ============================
// Exact R5 structure (measured 785us on qkv): CTA 128x128, BK=32, 8 warps of
// 64x32; A-frags via ldmatrix.x4, B-frags scalar LDS; cvt at staging.
#define DBM 128
#define DBN 128
#define DBK 32
#define DAS 36    // ldmatrix conflict-free
#define DBS 136   // ≡8 mod 32 -> scalar B-frag conflict-free

template<bool ROUND>
__global__ void __launch_bounds__(256) gemm_tf32(
    const float* __restrict__ A, int lda,
    const float* __restrict__ B, int ldb,
    float* __restrict__ Cm, int ldc,
    int K, const float* __restrict__ bias)
{
    __shared__ __align__(16) unsigned As[DBM * DAS];   // 18.4 KB
    __shared__ __align__(16) unsigned Bs[DBK * DBS];   // 17.4 KB

    const int m0 = blockIdx.y * DBM;
    const int n0 = blockIdx.x * DBN;
    const int tid = threadIdx.x;
    const int lane = tid & 31, wid = tid >> 5;
    const int wm = (wid & 1) * 64;
    const int wn = (wid >> 1) * 32;
    const int gi = lane >> 2, tg = lane & 3;

    float acc[4][4][4] = {};

    for (int k0 = 0; k0 < K; k0 += DBK) {
        // stage A tile 128x32 (cvt to tf32), STS.128
        #pragma unroll
        for (int it = 0; it < 4; it++) {
            int idx = tid + it * 256;
            int m = idx >> 3, q = idx & 7;
            float4 v = *(const float4*)(A + (size_t)(m0 + m) * lda + k0 + q * 4);
            uint4 t;
            t.x = f2tf32(v.x); t.y = f2tf32(v.y);
            t.z = f2tf32(v.z); t.w = f2tf32(v.w);
            *(uint4*)&As[m * DAS + q * 4] = t;
        }
        // stage B tile 32x128 (cvt to tf32), STS.128
        #pragma unroll
        for (int it = 0; it < 4; it++) {
            int idx = tid + it * 256;
            int k = idx >> 5, n4 = idx & 31;
            float4 v = *(const float4*)(B + (size_t)(k0 + k) * ldb + n0 + n4 * 4);
            uint4 t;
            t.x = f2tf32(v.x); t.y = f2tf32(v.y);
            t.z = f2tf32(v.z); t.w = f2tf32(v.w);
            *(uint4*)&Bs[k * DBS + n4 * 4] = t;
        }
        __syncthreads();

        #pragma unroll
        for (int ks = 0; ks < 4; ks++) {
            const int kk = ks * 8;
            unsigned a[4][4], b[4][2];
            #pragma unroll
            for (int i = 0; i < 4; i++)
                ldsmA(a[i], As, DAS, wm + i * 16, kk, lane);
            #pragma unroll
            for (int j = 0; j < 4; j++) {
                int n = wn + j * 8 + gi;
                b[j][0] = Bs[(kk + tg) * DBS + n];
                b[j][1] = Bs[(kk + tg + 4) * DBS + n];
            }
            #pragma unroll
            for (int i = 0; i < 4; i++)
                #pragma unroll
                for (int j = 0; j < 4; j++)
                    mma_tf32(acc[i][j], a[i], b[j]);
        }
        __syncthreads();
    }

    #pragma unroll
    for (int i = 0; i < 4; i++)
        #pragma unroll
        for (int j = 0; j < 4; j++) {
            int m = m0 + wm + i * 16 + gi;
            int n = n0 + wn + j * 8 + tg * 2;
            float b0 = __ldg(bias + n), b1 = __ldg(bias + n + 1);
            float v0 = acc[i][j][0] + b0, v1 = acc[i][j][1] + b1;
            float v2 = acc[i][j][2] + b0, v3 = acc[i][j][3] + b1;
            if (ROUND) {
                v0 = __uint_as_float(f2tf32(v0)); v1 = __uint_as_float(f2tf32(v1));
                v2 = __uint_as_float(f2tf32(v2)); v3 = __uint_as_float(f2tf32(v3));
            }
            *(float2*)&Cm[(size_t)m * ldc + n]       = make_float2(v0, v1);
            *(float2*)&Cm[(size_t)(m + 8) * ldc + n] = make_float2(v2, v3);
        }
}

// ===================== fused causal attention =====================
// R12 flash + work-proportional phase-1: warp columns cover [0,Ncol) exactly,
// so no warp idles on early (small-Ncol) causal blocks.
#define SS_S 260
#define QS_S 36
#define KN_S 36
#define VS_S 136
#define KV_BYTES (256*KN_S*4)
#define FL_SMEM (64*SS_S*4 + 64*QS_S*4 + KV_BYTES)   // 112640 B

__global__ void __launch_bounds__(256) flash_attn(
    const float* __restrict__ qkv, float* __restrict__ O)
{
    extern __shared__ __align__(16) unsigned char sm8[];
    float*    Ss = (float*)sm8;
    unsigned* Pu = (unsigned*)sm8;
    unsigned* Qs = (unsigned*)(sm8 + 64*SS_S*4);
    unsigned* Kn = (unsigned*)(sm8 + 64*SS_S*4 + 64*QS_S*4);
    unsigned* Vs = Kn;
    const unsigned uQs = (unsigned)__cvta_generic_to_shared(Qs);
    const unsigned uKn = (unsigned)__cvta_generic_to_shared(Kn);
    const unsigned uVs = uKn;

    const int b  = blockIdx.y;
    const int m0 = blockIdx.x * 64;
    const int Ncol = m0 + 64;
    const int tid = threadIdx.x;
    const int lane = tid & 31, wid = tid >> 5;
    const int gi = lane >> 2, tg = lane & 3;
    const float scale = 0.05103103630798288f;

    const float* Qp = qkv + ((size_t)b * SEQ + m0) * 1152;
    const float* Kp = qkv + (size_t)b * SEQ * 1152 + 384;
    const float* Vp = qkv + (size_t)b * SEQ * 1152 + 768;

    // ---------------- Phase 1: S = scale * Q @ K^T (work-proportional) ----------------
    const int wm  = (wid & 1) * 32;                 // 2 warps along M
    const int wn  = (wid >> 1) * (Ncol >> 2);       // 4 warp-cols span [0,Ncol)
    const int njt = Ncol >> 5;                      // n8-tile pairs per warp: 2..8

    float accS[2][8][4] = {};

    for (int k0 = 0; k0 < EMB; k0 += 32) {
        #pragma unroll
        for (int it = 0; it < 2; it++) {            // Q 64 rows x 8 chunks
            int idx = tid + it * 256;
            int m = idx >> 3, c4 = (idx & 7) << 2;
            cpa16(uQs + (unsigned)(m * QS_S + c4) * 4, Qp + (size_t)m * 1152 + k0 + c4);
        }
        for (int r = tid; r < Ncol * 8; r += 256) { // K Ncol rows x 8 chunks (n-major)
            int n = r >> 3, c4 = (r & 7) << 2;
            cpa16(uKn + (unsigned)(n * KN_S + c4) * 4, Kp + (size_t)n * 1152 + k0 + c4);
        }
        CP_COMMIT(); CP_WAIT0();
        __syncthreads();

        #pragma unroll
        for (int ks = 0; ks < 4; ks++) {
            const int kk = ks * 8;
            unsigned a[2][4], bf[8][2];
            ldsmA(a[0], Qs, QS_S, wm,      kk, lane);
            ldsmA(a[1], Qs, QS_S, wm + 16, kk, lane);
            #pragma unroll
            for (int j = 0; j < 8; j++)
                if (j < njt) {
                    int n = wn + j * 8 + gi;
                    bf[j][0] = Kn[n * KN_S + kk + tg];
                    bf[j][1] = Kn[n * KN_S + kk + tg + 4];
                }
            #pragma unroll
            for (int i = 0; i < 2; i++)
                #pragma unroll
                for (int j = 0; j < 8; j++)
                    if (j < njt)
                        mma_tf32(accS[i][j], a[i], bf[j]);
        }
        __syncthreads();
    }

    #pragma unroll
    for (int i = 0; i < 2; i++)
        #pragma unroll
        for (int j = 0; j < 8; j++)
            if (j < njt) {
                int ml = wm + i * 16 + gi;
                int nl = wn + j * 8 + tg * 2;
                int r0 = m0 + ml, r8 = r0 + 8;
                float v0 = accS[i][j][0] * scale, v1 = accS[i][j][1] * scale;
                float v2 = accS[i][j][2] * scale, v3 = accS[i][j][3] * scale;
                if (nl     > r0) v0 = -INFINITY;
                if (nl + 1 > r0) v1 = -INFINITY;
                if (nl     > r8) v2 = -INFINITY;
                if (nl + 1 > r8) v3 = -INFINITY;
                *(float2*)&Ss[ml * SS_S + nl]       = make_float2(v0, v1);
                *(float2*)&Ss[(ml + 8) * SS_S + nl] = make_float2(v2, v3);
            }
    __syncthreads();

    // ---------------- softmax: 4 lanes per row ----------------
    {
        const int row = tid >> 2, seg = tid & 3;
        const int base = row * SS_S + seg * 64;
        const bool act = (seg * 64 < Ncol);

        float mx = -INFINITY;
        if (act) {
            #pragma unroll
            for (int i = 0; i < 16; i++) {
                float4 v = *(float4*)&Ss[base + i * 4];
                mx = fmaxf(mx, fmaxf(fmaxf(v.x, v.y), fmaxf(v.z, v.w)));
            }
        }
        mx = fmaxf(mx, __shfl_xor_sync(0xffffffffu, mx, 1));
        mx = fmaxf(mx, __shfl_xor_sync(0xffffffffu, mx, 2));

        float s = 0.f;
        if (act) {
            #pragma unroll
            for (int i = 0; i < 16; i++) {
                float4 v = *(float4*)&Ss[base + i * 4];
                v.x = __expf(v.x - mx); v.y = __expf(v.y - mx);
                v.z = __expf(v.z - mx); v.w = __expf(v.w - mx);
                *(float4*)&Ss[base + i * 4] = v;
                s += v.x + v.y + v.z + v.w;
            }
        }
        s += __shfl_xor_sync(0xffffffffu, s, 1);
        s += __shfl_xor_sync(0xffffffffu, s, 2);
        float inv = 1.0f / s;

        if (act) {
            #pragma unroll
            for (int i = 0; i < 16; i++) {
                float4 v = *(float4*)&Ss[base + i * 4];
                uint4 t;
                t.x = f2tf32(v.x * inv); t.y = f2tf32(v.y * inv);
                t.z = f2tf32(v.z * inv); t.w = f2tf32(v.w * inv);
                *(uint4*)&Pu[base + i * 4] = t;
            }
        }
    }
    __syncthreads();

    // ---------------- Phase 2: O = P @ V ----------------
    const int wm2 = (wid & 1) * 32;
    const int wn2 = (wid >> 1) * 32;

    #pragma unroll
    for (int nc = 0; nc < 3; nc++) {
        float accO[2][4][4] = {};

        for (int k0 = 0; k0 < Ncol; k0 += 64) {
            #pragma unroll
            for (int it = 0; it < 8; it++) {
                int idx = tid + it * 256;
                int k = idx >> 5, c4 = (idx & 31) << 2;
                cpa16(uVs + (unsigned)(k * VS_S + c4) * 4,
                      Vp + (size_t)(k0 + k) * 1152 + nc * 128 + c4);
            }
            CP_COMMIT(); CP_WAIT0();
            __syncthreads();

            #pragma unroll
            for (int ks = 0; ks < 8; ks++) {
                const int kk = ks * 8;
                unsigned a[2][4], bf[4][2];
                ldsmA(a[0], Pu, SS_S, wm2,      k0 + kk, lane);
                ldsmA(a[1], Pu, SS_S, wm2 + 16, k0 + kk, lane);
                #pragma unroll
                for (int j = 0; j < 4; j++) {
                    int n = wn2 + j * 8 + gi;
                    bf[j][0] = Vs[(kk + tg) * VS_S + n];
                    bf[j][1] = Vs[(kk + tg + 4) * VS_S + n];
                }
                #pragma unroll
                for (int i = 0; i < 2; i++)
                    #pragma unroll
                    for (int j = 0; j < 4; j++)
                        mma_tf32(accO[i][j], a[i], bf[j]);
            }
            __syncthreads();
        }

        float* Op = O + ((size_t)b * SEQ + m0) * EMB + nc * 128;
        #pragma unroll
        for (int i = 0; i < 2; i++)
            #pragma unroll
            for (int j = 0; j < 4; j++) {
                int ml = wm2 + i * 16 + gi;
                int nl = wn2 + j * 8 + tg * 2;
                float v0 = __uint_as_float(f2tf32(accO[i][j][0]));
                float v1 = __uint_as_float(f2tf32(accO[i][j][1]));
                float v2 = __uint_as_float(f2tf32(accO[i][j][2]));
                float v3 = __uint_as_float(f2tf32(accO[i][j][3]));
                *(float2*)&Op[(size_t)ml * EMB + nl]       = make_float2(v0, v1);
                *(float2*)&Op[(size_t)(ml + 8) * EMB + nl] = make_float2(v2, v3);
            }
    }
}

extern "C" void kernel_launch(void* const* d_in, const int* in_sizes, int n_in,
                              void* d_out, int out_size)
{
    const float* x     = (const float*)d_in[0];
    const float* Wqkv  = (const float*)d_in[1];
    const float* bqkv  = (const float*)d_in[2];
    const float* Wproj = (const float*)d_in[3];
    const float* bproj = (const float*)d_in[4];
    float* out = (float*)d_out;

    float *qkv, *o;
    cudaGetSymbolAddress((void**)&qkv, g_qkv);
    cudaGetSymbolAddress((void**)&o,   g_o);

    cudaFuncSetAttribute(flash_attn, cudaFuncAttributeMaxDynamicSharedMemorySize, FL_SMEM);

    // 1) qkv = x @ W_qkv + b_qkv  (cvt at staging; output tf32-rounded)
    gemm_tf32<true><<<dim3(3 * EMB / DBN, MTOT / DBM), 256>>>(
        x, EMB, Wqkv, 3 * EMB, qkv, 3 * EMB, EMB, bqkv);

    // 2) fused causal attention -> g_o (tf32-rounded)
    flash_attn<<<dim3(SEQ / 64, BATCH), 256, FL_SMEM>>>(qkv, o);

    // 3) out = o @ W_proj + b_proj
    gemm_tf32<false><<<dim3(EMB / DBN, MTOT / DBM), 256>>>(
        o, EMB, Wproj, EMB, out, EMB, EMB, bproj);
}

// round 17
// speedup vs baseline: 1.4883x; 1.4883x over previous
#include <cuda_runtime.h>
#include <math.h>

#define BATCH 512
#define SEQ   256
#define EMB   384
#define MTOT  (BATCH*SEQ)

__device__ float g_qkv[(size_t)MTOT * 3 * EMB];   // tf32-rounded qkv
__device__ float g_o  [(size_t)MTOT * EMB];       // tf32-rounded attention out

__device__ __forceinline__ unsigned f2tf32(float v) {
    unsigned r;
    asm("cvt.rna.tf32.f32 %0, %1;" : "=r"(r) : "f"(v));
    return r;
}

__device__ __forceinline__ void mma_tf32(float c[4], const unsigned a[4], const unsigned b[2]) {
    asm volatile(
        "mma.sync.aligned.m16n8k8.row.col.f32.tf32.tf32.f32 "
        "{%0,%1,%2,%3}, {%4,%5,%6,%7}, {%8,%9}, {%0,%1,%2,%3};"
        : "+f"(c[0]), "+f"(c[1]), "+f"(c[2]), "+f"(c[3])
        : "r"(a[0]), "r"(a[1]), "r"(a[2]), "r"(a[3]), "r"(b[0]), "r"(b[1]));
}

__device__ __forceinline__ void ldsmA(unsigned a[4], const unsigned* base, int stride,
                                      int mbase, int kk0, int lane) {
    const unsigned* p = base + (size_t)(mbase + (lane & 15)) * stride + kk0 + ((lane >> 4) << 2);
    unsigned addr = (unsigned)__cvta_generic_to_shared(p);
    asm volatile("ldmatrix.sync.aligned.m8n8.x4.shared.b16 {%0,%1,%2,%3}, [%4];"
                 : "=r"(a[0]), "=r"(a[1]), "=r"(a[2]), "=r"(a[3]) : "r"(addr));
}

__device__ __forceinline__ void cpa16(unsigned dst, const void* src) {
    asm volatile("cp.async.cg.shared.global [%0], [%1], 16;" :: "r"(dst), "l"(src));
}
#define CP_COMMIT() asm volatile("cp.async.commit_group;")
#define CP_WAIT0()  asm volatile("cp.async.wait_group 0;")

// ============================ dense GEMM (qkv, proj) ============================
// Exact R5 structure (measured 785us on qkv): CTA 128x128, BK=32, 8 warps of
// 64x32; A-frags via ldmatrix.x4, B-frags scalar LDS; cvt at staging.
#define DBM 128
#define DBN 128
#define DBK 32
#define DAS 36    // ldmatrix conflict-free
#define DBS 136   // ≡8 mod 32 -> scalar B-frag conflict-free

template<bool ROUND>
__global__ void __launch_bounds__(256) gemm_tf32(
    const float* __restrict__ A, int lda,
    const float* __restrict__ B, int ldb,
    float* __restrict__ Cm, int ldc,
    int K, const float* __restrict__ bias)
{
    __shared__ __align__(16) unsigned As[DBM * DAS];   // 18.4 KB
    __shared__ __align__(16) unsigned Bs[DBK * DBS];   // 17.4 KB

    const int m0 = blockIdx.y * DBM;
    const int n0 = blockIdx.x * DBN;
    const int tid = threadIdx.x;
    const int lane = tid & 31, wid = tid >> 5;
    const int wm = (wid & 1) * 64;
    const int wn = (wid >> 1) * 32;
    const int gi = lane >> 2, tg = lane & 3;

    float acc[4][4][4] = {};

    for (int k0 = 0; k0 < K; k0 += DBK) {
        // stage A tile 128x32 (cvt to tf32), STS.128
        #pragma unroll
        for (int it = 0; it < 4; it++) {
            int idx = tid + it * 256;
            int m = idx >> 3, q = idx & 7;
            float4 v = *(const float4*)(A + (size_t)(m0 + m) * lda + k0 + q * 4);
            uint4 t;
            t.x = f2tf32(v.x); t.y = f2tf32(v.y);
            t.z = f2tf32(v.z); t.w = f2tf32(v.w);
            *(uint4*)&As[m * DAS + q * 4] = t;
        }
        // stage B tile 32x128 (cvt to tf32), STS.128
        #pragma unroll
        for (int it = 0; it < 4; it++) {
            int idx = tid + it * 256;
            int k = idx >> 5, n4 = idx & 31;
            float4 v = *(const float4*)(B + (size_t)(k0 + k) * ldb + n0 + n4 * 4);
            uint4 t;
            t.x = f2tf32(v.x); t.y = f2tf32(v.y);
            t.z = f2tf32(v.z); t.w = f2tf32(v.w);
            *(uint4*)&Bs[k * DBS + n4 * 4] = t;
        }
        __syncthreads();

        #pragma unroll
        for (int ks = 0; ks < 4; ks++) {
            const int kk = ks * 8;
            unsigned a[4][4], b[4][2];
            #pragma unroll
            for (int i = 0; i < 4; i++)
                ldsmA(a[i], As, DAS, wm + i * 16, kk, lane);
            #pragma unroll
            for (int j = 0; j < 4; j++) {
                int n = wn + j * 8 + gi;
                b[j][0] = Bs[(kk + tg) * DBS + n];
                b[j][1] = Bs[(kk + tg + 4) * DBS + n];
            }
            #pragma unroll
            for (int i = 0; i < 4; i++)
                #pragma unroll
                for (int j = 0; j < 4; j++)
                    mma_tf32(acc[i][j], a[i], b[j]);
        }
        __syncthreads();
    }

    #pragma unroll
    for (int i = 0; i < 4; i++)
        #pragma unroll
        for (int j = 0; j < 4; j++) {
            int m = m0 + wm + i * 16 + gi;
            int n = n0 + wn + j * 8 + tg * 2;
            float b0 = __ldg(bias + n), b1 = __ldg(bias + n + 1);
            float v0 = acc[i][j][0] + b0, v1 = acc[i][j][1] + b1;
            float v2 = acc[i][j][2] + b0, v3 = acc[i][j][3] + b1;
            if (ROUND) {
                v0 = __uint_as_float(f2tf32(v0)); v1 = __uint_as_float(f2tf32(v1));
                v2 = __uint_as_float(f2tf32(v2)); v3 = __uint_as_float(f2tf32(v3));
            }
            *(float2*)&Cm[(size_t)m * ldc + n]       = make_float2(v0, v1);
            *(float2*)&Cm[(size_t)(m + 8) * ldc + n] = make_float2(v2, v3);
        }
}

// ===================== fused causal attention (exact R12 version) =====================
#define SS_S 260
#define QS_S 36
#define KN_S 36
#define VS_S 136
#define KV_BYTES (256*KN_S*4)
#define FL_SMEM (64*SS_S*4 + 64*QS_S*4 + KV_BYTES)   // 112640 B

__global__ void __launch_bounds__(256) flash_attn(
    const float* __restrict__ qkv, float* __restrict__ O)
{
    extern __shared__ __align__(16) unsigned char sm8[];
    float*    Ss = (float*)sm8;
    unsigned* Pu = (unsigned*)sm8;
    unsigned* Qs = (unsigned*)(sm8 + 64*SS_S*4);
    unsigned* Kn = (unsigned*)(sm8 + 64*SS_S*4 + 64*QS_S*4);
    unsigned* Vs = Kn;
    const unsigned uQs = (unsigned)__cvta_generic_to_shared(Qs);
    const unsigned uKn = (unsigned)__cvta_generic_to_shared(Kn);
    const unsigned uVs = uKn;

    const int b  = blockIdx.y;
    const int m0 = blockIdx.x * 64;
    const int Ncol = m0 + 64;
    const int tid = threadIdx.x;
    const int lane = tid & 31, wid = tid >> 5;
    const int gi = lane >> 2, tg = lane & 3;
    const float scale = 0.05103103630798288f;

    const float* Qp = qkv + ((size_t)b * SEQ + m0) * 1152;
    const float* Kp = qkv + (size_t)b * SEQ * 1152 + 384;
    const float* Vp = qkv + (size_t)b * SEQ * 1152 + 768;

    // ---------------- Phase 1: S = scale * Q @ K^T (fixed layout + wact) ----------------
    const int wm = (wid & 1) * 32;           // 2 warps along M
    const int wn = (wid >> 1) * 64;          // 4 warps along N (fixed 64-wide)
    const bool wact = (wn < Ncol);

    float accS[2][8][4] = {};

    for (int k0 = 0; k0 < EMB; k0 += 32) {
        #pragma unroll
        for (int it = 0; it < 2; it++) {            // Q 64 rows x 8 chunks
            int idx = tid + it * 256;
            int m = idx >> 3, c4 = (idx & 7) << 2;
            cpa16(uQs + (unsigned)(m * QS_S + c4) * 4, Qp + (size_t)m * 1152 + k0 + c4);
        }
        for (int r = tid; r < Ncol * 8; r += 256) { // K Ncol rows x 8 chunks (n-major)
            int n = r >> 3, c4 = (r & 7) << 2;
            cpa16(uKn + (unsigned)(n * KN_S + c4) * 4, Kp + (size_t)n * 1152 + k0 + c4);
        }
        CP_COMMIT(); CP_WAIT0();
        __syncthreads();

        if (wact) {
            #pragma unroll
            for (int ks = 0; ks < 4; ks++) {
                const int kk = ks * 8;
                unsigned a[2][4], bf[8][2];
                ldsmA(a[0], Qs, QS_S, wm,      kk, lane);
                ldsmA(a[1], Qs, QS_S, wm + 16, kk, lane);
                #pragma unroll
                for (int j = 0; j < 8; j++) {
                    int n = wn + j * 8 + gi;
                    bf[j][0] = Kn[n * KN_S + kk + tg];
                    bf[j][1] = Kn[n * KN_S + kk + tg + 4];
                }
                #pragma unroll
                for (int i = 0; i < 2; i++)
                    #pragma unroll
                    for (int j = 0; j < 8; j++)
                        mma_tf32(accS[i][j], a[i], bf[j]);
            }
        }
        __syncthreads();
    }

    if (wact) {
        #pragma unroll
        for (int i = 0; i < 2; i++)
            #pragma unroll
            for (int j = 0; j < 8; j++) {
                int ml = wm + i * 16 + gi;
                int nl = wn + j * 8 + tg * 2;
                int r0 = m0 + ml, r8 = r0 + 8;
                float v0 = accS[i][j][0] * scale, v1 = accS[i][j][1] * scale;
                float v2 = accS[i][j][2] * scale, v3 = accS[i][j][3] * scale;
                if (nl     > r0) v0 = -INFINITY;
                if (nl + 1 > r0) v1 = -INFINITY;
                if (nl     > r8) v2 = -INFINITY;
                if (nl + 1 > r8) v3 = -INFINITY;
                *(float2*)&Ss[ml * SS_S + nl]       = make_float2(v0, v1);
                *(float2*)&Ss[(ml + 8) * SS_S + nl] = make_float2(v2, v3);
            }
    }
    __syncthreads();

    // ---------------- softmax: 4 lanes per row ----------------
    {
        const int row = tid >> 2, seg = tid & 3;
        const int base = row * SS_S + seg * 64;
        const bool act = (seg * 64 < Ncol);

        float mx = -INFINITY;
        if (act) {
            #pragma unroll
            for (int i = 0; i < 16; i++) {
                float4 v = *(float4*)&Ss[base + i * 4];
                mx = fmaxf(mx, fmaxf(fmaxf(v.x, v.y), fmaxf(v.z, v.w)));
            }
        }
        mx = fmaxf(mx, __shfl_xor_sync(0xffffffffu, mx, 1));
        mx = fmaxf(mx, __shfl_xor_sync(0xffffffffu, mx, 2));

        float s = 0.f;
        if (act) {
            #pragma unroll
            for (int i = 0; i < 16; i++) {
                float4 v = *(float4*)&Ss[base + i * 4];
                v.x = __expf(v.x - mx); v.y = __expf(v.y - mx);
                v.z = __expf(v.z - mx); v.w = __expf(v.w - mx);
                *(float4*)&Ss[base + i * 4] = v;
                s += v.x + v.y + v.z + v.w;
            }
        }
        s += __shfl_xor_sync(0xffffffffu, s, 1);
        s += __shfl_xor_sync(0xffffffffu, s, 2);
        float inv = 1.0f / s;

        if (act) {
            #pragma unroll
            for (int i = 0; i < 16; i++) {
                float4 v = *(float4*)&Ss[base + i * 4];
                uint4 t;
                t.x = f2tf32(v.x * inv); t.y = f2tf32(v.y * inv);
                t.z = f2tf32(v.z * inv); t.w = f2tf32(v.w * inv);
                *(uint4*)&Pu[base + i * 4] = t;
            }
        }
    }
    __syncthreads();

    // ---------------- Phase 2: O = P @ V ----------------
    const int wm2 = (wid & 1) * 32;
    const int wn2 = (wid >> 1) * 32;

    #pragma unroll
    for (int nc = 0; nc < 3; nc++) {
        float accO[2][4][4] = {};

        for (int k0 = 0; k0 < Ncol; k0 += 64) {
            #pragma unroll
            for (int it = 0; it < 8; it++) {
                int idx = tid + it * 256;
                int k = idx >> 5, c4 = (idx & 31) << 2;
                cpa16(uVs + (unsigned)(k * VS_S + c4) * 4,
                      Vp + (size_t)(k0 + k) * 1152 + nc * 128 + c4);
            }
            CP_COMMIT(); CP_WAIT0();
            __syncthreads();

            #pragma unroll
            for (int ks = 0; ks < 8; ks++) {
                const int kk = ks * 8;
                unsigned a[2][4], bf[4][2];
                ldsmA(a[0], Pu, SS_S, wm2,      k0 + kk, lane);
                ldsmA(a[1], Pu, SS_S, wm2 + 16, k0 + kk, lane);
                #pragma unroll
                for (int j = 0; j < 4; j++) {
                    int n = wn2 + j * 8 + gi;
                    bf[j][0] = Vs[(kk + tg) * VS_S + n];
                    bf[j][1] = Vs[(kk + tg + 4) * VS_S + n];
                }
                #pragma unroll
                for (int i = 0; i < 2; i++)
                    #pragma unroll
                    for (int j = 0; j < 4; j++)
                        mma_tf32(accO[i][j], a[i], bf[j]);
            }
            __syncthreads();
        }

        float* Op = O + ((size_t)b * SEQ + m0) * EMB + nc * 128;
        #pragma unroll
        for (int i = 0; i < 2; i++)
            #pragma unroll
            for (int j = 0; j < 4; j++) {
                int ml = wm2 + i * 16 + gi;
                int nl = wn2 + j * 8 + tg * 2;
                float v0 = __uint_as_float(f2tf32(accO[i][j][0]));
                float v1 = __uint_as_float(f2tf32(accO[i][j][1]));
                float v2 = __uint_as_float(f2tf32(accO[i][j][2]));
                float v3 = __uint_as_float(f2tf32(accO[i][j][3]));
                *(float2*)&Op[(size_t)ml * EMB + nl]       = make_float2(v0, v1);
                *(float2*)&Op[(size_t)(ml + 8) * EMB + nl] = make_float2(v2, v3);
            }
    }
}

extern "C" void kernel_launch(void* const* d_in, const int* in_sizes, int n_in,
                              void* d_out, int out_size)
{
    const float* x     = (const float*)d_in[0];
    const float* Wqkv  = (const float*)d_in[1];
    const float* bqkv  = (const float*)d_in[2];
    const float* Wproj = (const float*)d_in[3];
    const float* bproj = (const float*)d_in[4];
    float* out = (float*)d_out;

    float *qkv, *o;
    cudaGetSymbolAddress((void**)&qkv, g_qkv);
    cudaGetSymbolAddress((void**)&o,   g_o);

    cudaFuncSetAttribute(flash_attn, cudaFuncAttributeMaxDynamicSharedMemorySize, FL_SMEM);

    // 1) qkv = x @ W_qkv + b_qkv  (cvt at staging; output tf32-rounded)
    gemm_tf32<true><<<dim3(3 * EMB / DBN, MTOT / DBM), 256>>>(
        x, EMB, Wqkv, 3 * EMB, qkv, 3 * EMB, EMB, bqkv);

    // 2) fused causal attention -> g_o (tf32-rounded)
    flash_attn<<<dim3(SEQ / 64, BATCH), 256, FL_SMEM>>>(qkv, o);

    // 3) out = o @ W_proj + b_proj  (cvt at staging)
    gemm_tf32<false><<<dim3(EMB / DBN, MTOT / DBM), 256>>>(
        o, EMB, Wproj, EMB, out, EMB, EMB, bproj);
}